// round 2
// baseline (speedup 1.0000x reference)
#include <cuda_runtime.h>
#include <math.h>

#define N_NODES 4096
#define F_IN    256
#define F_OUT   512
#define HEADS   8
#define DH      64

// Scratch (no allocations allowed): h = x@W^T, q = h@A  (8 MB each)
__device__ float g_h[N_NODES * F_OUT];
__device__ float g_q[N_NODES * F_OUT];

// ---------------------------------------------------------------------------
// Kernel 1: h[n][o] = sum_k x[n][k] * W[o][k]   (M=4096, N=512, K=256)
// 64x64 tile, BK=16, 256 threads, 4x4 micro-tile
// ---------------------------------------------------------------------------
__global__ __launch_bounds__(256) void k_gemm_xwT(const float* __restrict__ X,
                                                  const float* __restrict__ W) {
    __shared__ float sX[16][68];  // [k][m]
    __shared__ float sW[16][68];  // [k][o]
    const int tid = threadIdx.x;
    const int ty = tid >> 4, tx = tid & 15;
    const int m0 = blockIdx.x * 64, n0 = blockIdx.y * 64;

    float acc[4][4] = {};

    for (int k0 = 0; k0 < F_IN; k0 += 16) {
        {
            const int r  = tid >> 2;          // 0..63
            const int kk = (tid & 3) * 4;     // 0,4,8,12
            float4 v = *(const float4*)&X[(m0 + r) * F_IN + k0 + kk];
            sX[kk + 0][r] = v.x; sX[kk + 1][r] = v.y;
            sX[kk + 2][r] = v.z; sX[kk + 3][r] = v.w;
            float4 w = *(const float4*)&W[(n0 + r) * F_IN + k0 + kk];
            sW[kk + 0][r] = w.x; sW[kk + 1][r] = w.y;
            sW[kk + 2][r] = w.z; sW[kk + 3][r] = w.w;
        }
        __syncthreads();
        #pragma unroll
        for (int kk = 0; kk < 16; kk++) {
            float a[4], b[4];
            #pragma unroll
            for (int i = 0; i < 4; i++) a[i] = sX[kk][ty * 4 + i];
            #pragma unroll
            for (int j = 0; j < 4; j++) b[j] = sW[kk][tx * 4 + j];
            #pragma unroll
            for (int i = 0; i < 4; i++)
                #pragma unroll
                for (int j = 0; j < 4; j++)
                    acc[i][j] = fmaf(a[i], b[j], acc[i][j]);
        }
        __syncthreads();
    }
    #pragma unroll
    for (int i = 0; i < 4; i++) {
        float4 v = make_float4(acc[i][0], acc[i][1], acc[i][2], acc[i][3]);
        *(float4*)&g_h[(m0 + ty * 4 + i) * F_OUT + n0 + tx * 4] = v;
    }
}

// ---------------------------------------------------------------------------
// Kernel 2: q[n][h*64+e] = sum_d h[n][h*64+d] * A[h][d][e]
// grid = (4096/64, HEADS), 256 threads, K=64 in one shot
// ---------------------------------------------------------------------------
__global__ __launch_bounds__(256) void k_gemm_hA(const float* __restrict__ A) {
    __shared__ float sH[64][65];  // [d][n_local]  (transposed)
    __shared__ float sA[64][65];  // [d][e]
    const int tid = threadIdx.x;
    const int ty = tid >> 4, tx = tid & 15;
    const int head = blockIdx.y;
    const int n0 = blockIdx.x * 64;

    {
        const int r  = tid >> 2;          // 0..63  (n-row for H, d-row for A)
        const int c0 = (tid & 3) * 16;
        #pragma unroll
        for (int cc = 0; cc < 16; cc += 4) {
            float4 v = *(const float4*)&g_h[(n0 + r) * F_OUT + head * DH + c0 + cc];
            sH[c0 + cc + 0][r] = v.x; sH[c0 + cc + 1][r] = v.y;
            sH[c0 + cc + 2][r] = v.z; sH[c0 + cc + 3][r] = v.w;
            float4 a = *(const float4*)&A[head * DH * DH + r * DH + c0 + cc];
            sA[r][c0 + cc + 0] = a.x; sA[r][c0 + cc + 1] = a.y;
            sA[r][c0 + cc + 2] = a.z; sA[r][c0 + cc + 3] = a.w;
        }
    }
    __syncthreads();

    float acc[4][4] = {};
    #pragma unroll 16
    for (int d = 0; d < DH; d++) {
        float a[4], b[4];
        #pragma unroll
        for (int i = 0; i < 4; i++) a[i] = sH[d][ty * 4 + i];
        #pragma unroll
        for (int j = 0; j < 4; j++) b[j] = sA[d][tx * 4 + j];
        #pragma unroll
        for (int i = 0; i < 4; i++)
            #pragma unroll
            for (int j = 0; j < 4; j++)
                acc[i][j] = fmaf(a[i], b[j], acc[i][j]);
    }
    #pragma unroll
    for (int i = 0; i < 4; i++) {
        float4 v = make_float4(acc[i][0], acc[i][1], acc[i][2], acc[i][3]);
        *(float4*)&g_q[(n0 + ty * 4 + i) * F_OUT + head * DH + tx * 4] = v;
    }
}

// ---------------------------------------------------------------------------
// Kernel 3: fused attention (flash-style).
// Per block: 64 queries x 1 head. Loop over key tiles of 64.
//   S = Q K^T (d=64); LeakyReLU(0.2); online softmax; O += P * V  (V == K tile)
// 256 threads as 16x16, each owns a 4x4 patch:
//   rows r = ty*4+i (queries), cols c = tx*4+j (keys) for S;
//   rows r, dims = tx*4+j for O.
// P·V uses warp shuffles (P lives distributed across the 16 tx lanes).
// ---------------------------------------------------------------------------
__global__ __launch_bounds__(256) void k_attn(float* __restrict__ Out) {
    __shared__ float sQ[64][65];  // [q_local][dim]
    __shared__ float sK[64][65];  // [k_local][dim]  (also the V tile)
    const int tid  = threadIdx.x;
    const int ty   = tid >> 4, tx = tid & 15;
    const int lane = tid & 31;
    const int head = blockIdx.y;
    const int q0   = blockIdx.x * 64;

    // Load Q tile
    {
        const int r  = tid >> 2;
        const int c0 = (tid & 3) * 16;
        #pragma unroll
        for (int cc = 0; cc < 16; cc += 4) {
            float4 v = *(const float4*)&g_q[(q0 + r) * F_OUT + head * DH + c0 + cc];
            sQ[r][c0 + cc + 0] = v.x; sQ[r][c0 + cc + 1] = v.y;
            sQ[r][c0 + cc + 2] = v.z; sQ[r][c0 + cc + 3] = v.w;
        }
    }

    float acc[4][4] = {};
    float mrow[4], lrow[4];
    #pragma unroll
    for (int i = 0; i < 4; i++) { mrow[i] = -INFINITY; lrow[i] = 0.f; }

    for (int key0 = 0; key0 < N_NODES; key0 += 64) {
        __syncthreads();   // prior-iter PV readers done (and sQ visible on iter 0)
        {
            const int r  = tid >> 2;
            const int c0 = (tid & 3) * 16;
            #pragma unroll
            for (int cc = 0; cc < 16; cc += 4) {
                float4 v = *(const float4*)&g_h[(key0 + r) * F_OUT + head * DH + c0 + cc];
                sK[r][c0 + cc + 0] = v.x; sK[r][c0 + cc + 1] = v.y;
                sK[r][c0 + cc + 2] = v.z; sK[r][c0 + cc + 3] = v.w;
            }
        }
        __syncthreads();

        // ---- S = Q K^T ----
        float s[4][4] = {};
        #pragma unroll 16
        for (int k = 0; k < DH; k++) {
            float a[4], b[4];
            #pragma unroll
            for (int i = 0; i < 4; i++) a[i] = sQ[ty * 4 + i][k];
            #pragma unroll
            for (int j = 0; j < 4; j++) b[j] = sK[tx * 4 + j][k];
            #pragma unroll
            for (int i = 0; i < 4; i++)
                #pragma unroll
                for (int j = 0; j < 4; j++)
                    s[i][j] = fmaf(a[i], b[j], s[i][j]);
        }

        // ---- LeakyReLU(0.2) + online softmax (rows span 16 tx lanes) ----
        #pragma unroll
        for (int i = 0; i < 4; i++) {
            #pragma unroll
            for (int j = 0; j < 4; j++)
                s[i][j] = s[i][j] >= 0.f ? s[i][j] : 0.2f * s[i][j];

            float tm = fmaxf(fmaxf(s[i][0], s[i][1]), fmaxf(s[i][2], s[i][3]));
            #pragma unroll
            for (int off = 8; off >= 1; off >>= 1)
                tm = fmaxf(tm, __shfl_xor_sync(0xffffffffu, tm, off));

            const float mnew  = fmaxf(mrow[i], tm);
            const float scale = __expf(mrow[i] - mnew);   // 0 on first tile
            mrow[i] = mnew;

            float rsum = 0.f;
            #pragma unroll
            for (int j = 0; j < 4; j++) {
                s[i][j] = __expf(s[i][j] - mnew);
                rsum += s[i][j];
            }
            #pragma unroll
            for (int off = 8; off >= 1; off >>= 1)
                rsum += __shfl_xor_sync(0xffffffffu, rsum, off);

            lrow[i] = lrow[i] * scale + rsum;
            #pragma unroll
            for (int j = 0; j < 4; j++) acc[i][j] *= scale;
        }

        // ---- O += P * V  (P via shuffle from owning tx lane; V = sK) ----
        const int laneHi = lane & 16;   // stay within own ty row-group
        for (int cb = 0; cb < 64; cb += 16) {
            #pragma unroll
            for (int cc = 0; cc < 16; cc++) {
                const int c = cb + cc;
                const int srcLane = laneHi | (c >> 2);
                float p0 = __shfl_sync(0xffffffffu, s[0][cc & 3], srcLane);
                float p1 = __shfl_sync(0xffffffffu, s[1][cc & 3], srcLane);
                float p2 = __shfl_sync(0xffffffffu, s[2][cc & 3], srcLane);
                float p3 = __shfl_sync(0xffffffffu, s[3][cc & 3], srcLane);
                float v0 = sK[c][tx * 4 + 0];
                float v1 = sK[c][tx * 4 + 1];
                float v2 = sK[c][tx * 4 + 2];
                float v3 = sK[c][tx * 4 + 3];
                acc[0][0] = fmaf(p0, v0, acc[0][0]); acc[0][1] = fmaf(p0, v1, acc[0][1]);
                acc[0][2] = fmaf(p0, v2, acc[0][2]); acc[0][3] = fmaf(p0, v3, acc[0][3]);
                acc[1][0] = fmaf(p1, v0, acc[1][0]); acc[1][1] = fmaf(p1, v1, acc[1][1]);
                acc[1][2] = fmaf(p1, v2, acc[1][2]); acc[1][3] = fmaf(p1, v3, acc[1][3]);
                acc[2][0] = fmaf(p2, v0, acc[2][0]); acc[2][1] = fmaf(p2, v1, acc[2][1]);
                acc[2][2] = fmaf(p2, v2, acc[2][2]); acc[2][3] = fmaf(p2, v3, acc[2][3]);
                acc[3][0] = fmaf(p3, v0, acc[3][0]); acc[3][1] = fmaf(p3, v1, acc[3][1]);
                acc[3][2] = fmaf(p3, v2, acc[3][2]); acc[3][3] = fmaf(p3, v3, acc[3][3]);
            }
        }
    }

    // ---- finalize: divide by softmax denominator, write out ----
    #pragma unroll
    for (int i = 0; i < 4; i++) {
        const float inv = 1.0f / lrow[i];
        float4 v = make_float4(acc[i][0] * inv, acc[i][1] * inv,
                               acc[i][2] * inv, acc[i][3] * inv);
        *(float4*)&Out[(q0 + ty * 4 + i) * F_OUT + head * DH + tx * 4] = v;
    }
}

// ---------------------------------------------------------------------------
extern "C" void kernel_launch(void* const* d_in, const int* in_sizes, int n_in,
                              void* d_out, int out_size) {
    const float* x = (const float*)d_in[0];
    // d_in[1] = adj (int32) — unused by the reference forward
    const float* W = (const float*)d_in[2];
    const float* A = (const float*)d_in[3];
    float* out = (float*)d_out;

    k_gemm_xwT<<<dim3(N_NODES / 64, F_OUT / 64), 256>>>(x, W);
    k_gemm_hA<<<dim3(N_NODES / 64, HEADS), 256>>>(A);
    k_attn<<<dim3(N_NODES / 64, HEADS), 256>>>(out);
}